// round 1
// baseline (speedup 1.0000x reference)
#include <cuda_runtime.h>

#define VSZ 20000
#define MM  32
#define EE  128
#define NN  8192
#define LL  64
#define CC  128

// ---------------- scratch (device globals; no allocation allowed) -----------
__device__ float g_Q[NN*EE];             // table @ wq.T + bq
__device__ float g_K[NN*EE];             // table @ wk.T + bk
__device__ float g_V[NN*EE];             // table @ wv.T + bv
__device__ float g_wemb[VSZ*EE];         // word embeddings
__device__ float g_wT[(3+4+5)*EE*CC];    // conv weights transposed to [j][e][c] per k

// ---------------- f32x2 helpers (Blackwell packed fp32) ---------------------
__device__ __forceinline__ unsigned long long pk2(float x, float y){
    unsigned long long r;
    asm("mov.b64 %0, {%1,%2};" : "=l"(r) : "f"(x), "f"(y));
    return r;
}
__device__ __forceinline__ void upk2(unsigned long long v, float &x, float &y){
    asm("mov.b64 {%0,%1}, %2;" : "=f"(x), "=f"(y) : "l"(v));
}
__device__ __forceinline__ void ffma2(unsigned long long &d, unsigned long long a, unsigned long long b){
    asm("fma.rn.f32x2 %0, %1, %2, %0;" : "+l"(d) : "l"(a), "l"(b));
}

// ============================================================================
// Kernel 1: project news table once: Qn/Kn/Vn = table @ W.T + b
// grid = N blocks, 128 threads; weights (196KB) stay hot in L1 across blocks.
// ============================================================================
__global__ void proj_kernel(const float* __restrict__ table,
                            const float* __restrict__ ipw,
                            const float* __restrict__ ipb){
    int n = blockIdx.x, e = threadIdx.x;
    __shared__ float4 sX[EE/4];
    ((float*)sX)[e] = table[n*EE + e];
    __syncthreads();
    const float4* rq = (const float4*)(ipw + (size_t)e*EE);
    const float4* rk = (const float4*)(ipw + (size_t)(EE + e)*EE);
    const float4* rv = (const float4*)(ipw + (size_t)(2*EE + e)*EE);
    float aq = 0.f, ak = 0.f, av = 0.f;
    #pragma unroll 8
    for (int j = 0; j < EE/4; j++){
        float4 x = sX[j];
        float4 q = rq[j], k = rk[j], v = rv[j];
        aq += q.x*x.x + q.y*x.y + q.z*x.z + q.w*x.w;
        ak += k.x*x.x + k.y*x.y + k.z*x.z + k.w*x.w;
        av += v.x*x.x + v.y*x.y + v.z*x.z + v.w*x.w;
    }
    g_Q[n*EE+e] = aq + ipb[e];
    g_K[n*EE+e] = ak + ipb[EE + e];
    g_V[n*EE+e] = av + ipb[2*EE + e];
}

// ============================================================================
// Kernel 2: transpose conv weights  w[c][e][j]  ->  gwT_k[j][e][c]
// (one-time tiny kernel; makes conv shared-memory staging coalesced +
//  STS conflict-free)
// ============================================================================
__global__ void wtrans_kernel(const float* __restrict__ w3,
                              const float* __restrict__ w4,
                              const float* __restrict__ w5){
    int idx = blockIdx.x*256 + threadIdx.x;            // 0 .. 196607
    if (idx < 3*16384){
        int j = idx >> 14, r = idx & 16383, e = r >> 7, c = r & 127;
        g_wT[idx] = w3[(c*EE + e)*3 + j];
    } else if (idx < 7*16384){
        int o = idx - 3*16384;
        int j = o >> 14, r = o & 16383, e = r >> 7, c = r & 127;
        g_wT[idx] = w4[(c*EE + e)*4 + j];
    } else if (idx < 12*16384){
        int o = idx - 7*16384;
        int j = o >> 14, r = o & 16383, e = r >> 7, c = r & 127;
        g_wT[idx] = w5[(c*EE + e)*5 + j];
    }
}

// ============================================================================
// Kernel 3: per-word 1-query MHA using precomputed projected tables.
// One block (128 threads) per word; warp h == head h (Dh = 32).
// ============================================================================
__global__ void attn_kernel(const int* __restrict__ w2n,
                            const int* __restrict__ w2nlen,
                            const float* __restrict__ opw,
                            const float* __restrict__ opb){
    int v = blockIdx.x, e = threadIdx.x;
    int h = e >> 5, lane = e & 31;
    int ln = w2nlen[v];
    if (ln == 0){ g_wemb[v*EE + e] = 0.f; return; }   // uniform branch

    __shared__ int   sIdx[MM];
    __shared__ float sQ[EE], sAttn[EE], sO[EE];
    __shared__ float sK[MM*129], sV[MM*129];          // pad 129: conflict-free

    if (e < MM) sIdx[e] = (e < ln) ? w2n[v*MM + e] : 0;
    __syncthreads();

    float qa = 0.f;
    for (int m = 0; m < ln; m++){
        int r = sIdx[m];
        qa += g_Q[r*EE + e];
        sK[m*129 + e] = g_K[r*EE + e];
        sV[m*129 + e] = g_V[r*EE + e];
    }
    sQ[e] = qa / (float)ln;    // mean of (row+bq) == mean@wq + bq
    __syncthreads();

    // scores[h][m], m = lane, warp h
    float s = -1e9f;
    if (lane < ln){
        s = 0.f;
        int base = h*32;
        #pragma unroll 8
        for (int d = 0; d < 32; d++)
            s += sQ[base + d] * sK[lane*129 + base + d];
        s *= 0.17677669529663687f;                    // 1/sqrt(32)
    }
    // warp softmax over m
    float mx = s;
    #pragma unroll
    for (int o = 16; o > 0; o >>= 1) mx = fmaxf(mx, __shfl_xor_sync(0xffffffffu, mx, o));
    float ex = (lane < ln) ? __expf(s - mx) : 0.f;
    float sm = ex;
    #pragma unroll
    for (int o = 16; o > 0; o >>= 1) sm += __shfl_xor_sync(0xffffffffu, sm, o);
    sAttn[e] = ex / sm;
    __syncthreads();

    // o[e] = sum_m attn[h][m] * V[m][e]
    float oa = 0.f;
    for (int m = 0; m < ln; m++)
        oa += sAttn[h*32 + m] * sV[m*129 + e];
    sO[e] = oa;
    __syncthreads();

    // out projection
    float r = opb[e];
    const float4* w4 = (const float4*)(opw + (size_t)e*EE);
    const float4* o4 = (const float4*)sO;
    #pragma unroll 8
    for (int j = 0; j < EE/4; j++){
        float4 w = w4[j]; float4 o = o4[j];
        r += w.x*o.x + w.y*o.y + w.z*o.z + w.w*o.w;
    }
    g_wemb[v*EE + e] = r;
}

// ============================================================================
// Kernel 4: gather doc + conv(3,4,5) + relu + maxpool + fc, fused.
// One block (256 threads) per news item. Implicit GEMM with f32x2 FMAs.
// Thread tile: 2 t-rows (tq, tq+32) x 16 channels (8 packed pairs).
// ============================================================================
#define DOCPAD   129
#define DOC_OFF  0
#define WS_OFF   9032                      // 70*129 rounded to 16B alignment
#define PART_OFF (WS_OFF + 5*32*128)       // 29512
#define POOL_OFF (PART_OFF + 32*128)       // 33608
#define SMEM_FLT (POOL_OFF + 3*128)        // 33992 floats = 135968 bytes

__global__ __launch_bounds__(256, 1)
void conv_kernel(const int*   __restrict__ news_words,
                 const float* __restrict__ b3,
                 const float* __restrict__ b4,
                 const float* __restrict__ b5,
                 const float* __restrict__ fcw,
                 const float* __restrict__ fcb,
                 float*       __restrict__ out){
    extern __shared__ float sh[];
    int n = blockIdx.x, tid = threadIdx.x;
    int tq = tid >> 3;            // 0..31  (owns t = tq and t = tq+32)
    int cq = tid & 7;             // 0..7   (owns c = cq*16 .. cq*16+15)

    // stage doc tile [64][128] (gather rows of g_wemb), zero-pad rows 64..69
    for (int i = tid; i < LL*EE; i += 256){
        int t = i >> 7, e = i & 127;
        int w = news_words[n*LL + t];
        sh[DOC_OFF + t*DOCPAD + e] = g_wemb[w*EE + e];
    }
    for (int i = tid; i < 6*DOCPAD; i += 256)
        sh[DOC_OFF + LL*DOCPAD + i] = 0.f;

    const float* bks[3] = {b3, b4, b5};
    int wtoff = 0;
    for (int kk = 0; kk < 3; kk++){
        const int K = kk + 3;
        unsigned long long acc0[8], acc1[8];
        #pragma unroll
        for (int p = 0; p < 8; p++){ acc0[p] = 0ull; acc1[p] = 0ull; }

        for (int ec = 0; ec < 4; ec++){              // e chunks of 32
            __syncthreads();                          // protects doc + prior wS use
            int tot = K*4096;
            for (int i = tid; i < tot; i += 256){     // stage wS[j][ei][c]
                int j = i >> 12, r = i & 4095;
                int ei = r >> 7, c = r & 127;
                sh[WS_OFF + (j*32 + ei)*128 + c] =
                    g_wT[wtoff + (j*EE + ec*32 + ei)*128 + c];
            }
            __syncthreads();

            for (int j = 0; j < K; j++){
                const float* dp0  = &sh[DOC_OFF + (tq      + j)*DOCPAD + ec*32];
                const float* dp1  = &sh[DOC_OFF + (tq + 32 + j)*DOCPAD + ec*32];
                const float* wrow = &sh[WS_OFF + j*32*128 + cq*16];
                #pragma unroll 2
                for (int e = 0; e < 32; e++){
                    float d0v = dp0[e];
                    float d1v = dp1[e];
                    unsigned long long a0 = pk2(d0v, d0v);
                    unsigned long long a1 = pk2(d1v, d1v);
                    const unsigned long long* wp =
                        (const unsigned long long*)(wrow + e*128);
                    #pragma unroll
                    for (int p = 0; p < 8; p++){
                        unsigned long long b = wp[p];
                        ffma2(acc0[p], a0, b);
                        ffma2(acc1[p], a1, b);
                    }
                }
            }
        }

        // local max over this thread's two t rows (masked), write partials
        __syncthreads();
        bool t1ok = (tq + 32) <= (LL - K);
        #pragma unroll
        for (int p = 0; p < 8; p++){
            float a, b, c, d;
            upk2(acc0[p], a, b);
            upk2(acc1[p], c, d);
            float m0 = t1ok ? fmaxf(a, c) : a;
            float m1 = t1ok ? fmaxf(b, d) : b;
            sh[PART_OFF + tq*128 + cq*16 + 2*p    ] = m0;
            sh[PART_OFF + tq*128 + cq*16 + 2*p + 1] = m1;
        }
        __syncthreads();
        if (tid < 128){                               // reduce 32 tq partials
            float m = sh[PART_OFF + tid];
            #pragma unroll 4
            for (int q = 1; q < 32; q++)
                m = fmaxf(m, sh[PART_OFF + q*128 + tid]);
            // max_t relu(y+b) == relu(b + max_t y)
            sh[POOL_OFF + kk*128 + tid] = fmaxf(m + bks[kk][tid], 0.f);
        }
        wtoff += K*16384;
    }
    __syncthreads();

    // fc: out[n][e] = fc_b[e] + pooled . fc_w[e]
    if (tid < 128){
        float acc = fcb[tid];
        const float4* w4 = (const float4*)(fcw + (size_t)tid*384);
        const float4* p4 = (const float4*)&sh[POOL_OFF];
        #pragma unroll 8
        for (int r = 0; r < 96; r++){
            float4 w = w4[r]; float4 p = p4[r];
            acc += w.x*p.x + w.y*p.y + w.z*p.z + w.w*p.w;
        }
        out[n*EE + tid] = acc;
    }
}

// ============================================================================
extern "C" void kernel_launch(void* const* d_in, const int* in_sizes, int n_in,
                              void* d_out, int out_size){
    const int*   w2n   = (const int*)  d_in[0];
    const int*   w2nl  = (const int*)  d_in[1];
    const int*   nws   = (const int*)  d_in[2];
    const float* table = (const float*)d_in[3];
    const float* ipw   = (const float*)d_in[4];
    const float* ipb   = (const float*)d_in[5];
    const float* opw   = (const float*)d_in[6];
    const float* opb   = (const float*)d_in[7];
    const float* w3    = (const float*)d_in[8];
    const float* b3    = (const float*)d_in[9];
    const float* w4    = (const float*)d_in[10];
    const float* b4    = (const float*)d_in[11];
    const float* w5    = (const float*)d_in[12];
    const float* b5    = (const float*)d_in[13];
    const float* fcw   = (const float*)d_in[14];
    const float* fcb   = (const float*)d_in[15];
    float* out = (float*)d_out;

    cudaFuncSetAttribute(conv_kernel,
                         cudaFuncAttributeMaxDynamicSharedMemorySize,
                         SMEM_FLT*4);

    proj_kernel  <<<NN, 128>>>(table, ipw, ipb);
    wtrans_kernel<<<768, 256>>>(w3, w4, w5);
    attn_kernel  <<<VSZ, 128>>>(w2n, w2nl, opw, opb);
    conv_kernel  <<<NN, 256, SMEM_FLT*4>>>(nws, b3, b4, b5, fcw, fcb, out);
}

// round 2
// speedup vs baseline: 6.5507x; 6.5507x over previous
#include <cuda_runtime.h>
#include <cstdint>

#define VSZ 20000
#define MM  32
#define EE  128
#define NN  8192
#define LL  64
#define CC  128

typedef unsigned long long ull;

// ---------------- scratch (device globals; no allocation allowed) -----------
__device__ float g_Q[NN*EE];
__device__ float g_K[NN*EE];
__device__ float g_V[NN*EE];
__device__ float g_wemb[VSZ*EE];
__device__ float g_wT[(3+4+5)*EE*CC];    // [k][j][e][c], c contiguous

// ---------------- f32x2 helpers ---------------------------------------------
__device__ __forceinline__ ull pk2(float x, float y){
    ull r; asm("mov.b64 %0, {%1,%2};" : "=l"(r) : "f"(x), "f"(y)); return r;
}
__device__ __forceinline__ void upk2(ull v, float &x, float &y){
    asm("mov.b64 {%0,%1}, %2;" : "=f"(x), "=f"(y) : "l"(v));
}
__device__ __forceinline__ void ffma2(ull &d, ull a, ull b){
    asm("fma.rn.f32x2 %0, %1, %2, %0;" : "+l"(d) : "l"(a), "l"(b));
}
__device__ __forceinline__ void cpasync16(uint32_t d, const float* s){
    asm volatile("cp.async.cg.shared.global [%0], [%1], 16;" :: "r"(d), "l"(s));
}

// ============================================================================
// Kernel 1: project news table once: Qn/Kn/Vn = table @ W.T + b
// ============================================================================
__global__ void proj_kernel(const float* __restrict__ table,
                            const float* __restrict__ ipw,
                            const float* __restrict__ ipb){
    int n = blockIdx.x, e = threadIdx.x;
    __shared__ float4 sX[EE/4];
    ((float*)sX)[e] = table[n*EE + e];
    __syncthreads();
    const float4* rq = (const float4*)(ipw + (size_t)e*EE);
    const float4* rk = (const float4*)(ipw + (size_t)(EE + e)*EE);
    const float4* rv = (const float4*)(ipw + (size_t)(2*EE + e)*EE);
    float aq = 0.f, ak = 0.f, av = 0.f;
    #pragma unroll 8
    for (int j = 0; j < EE/4; j++){
        float4 x = sX[j];
        float4 q = rq[j], k = rk[j], v = rv[j];
        aq += q.x*x.x + q.y*x.y + q.z*x.z + q.w*x.w;
        ak += k.x*x.x + k.y*x.y + k.z*x.z + k.w*x.w;
        av += v.x*x.x + v.y*x.y + v.z*x.z + v.w*x.w;
    }
    g_Q[n*EE+e] = aq + ipb[e];
    g_K[n*EE+e] = ak + ipb[EE + e];
    g_V[n*EE+e] = av + ipb[2*EE + e];
}

// ============================================================================
// Kernel 2: transpose conv weights  w[c][e][j]  ->  g_wT[k][j][e][c]
// ============================================================================
__global__ void wtrans_kernel(const float* __restrict__ w3,
                              const float* __restrict__ w4,
                              const float* __restrict__ w5){
    int idx = blockIdx.x*256 + threadIdx.x;
    if (idx < 3*16384){
        int j = idx >> 14, r = idx & 16383, e = r >> 7, c = r & 127;
        g_wT[idx] = w3[(c*EE + e)*3 + j];
    } else if (idx < 7*16384){
        int o = idx - 3*16384;
        int j = o >> 14, r = o & 16383, e = r >> 7, c = r & 127;
        g_wT[idx] = w4[(c*EE + e)*4 + j];
    } else if (idx < 12*16384){
        int o = idx - 7*16384;
        int j = o >> 14, r = o & 16383, e = r >> 7, c = r & 127;
        g_wT[idx] = w5[(c*EE + e)*5 + j];
    }
}

// ============================================================================
// Kernel 3: per-word 1-query MHA using precomputed projected tables.
// ============================================================================
__global__ void attn_kernel(const int* __restrict__ w2n,
                            const int* __restrict__ w2nlen,
                            const float* __restrict__ opw,
                            const float* __restrict__ opb){
    int v = blockIdx.x, e = threadIdx.x;
    int h = e >> 5, lane = e & 31;
    int ln = w2nlen[v];
    if (ln == 0){ g_wemb[v*EE + e] = 0.f; return; }

    __shared__ int   sIdx[MM];
    __shared__ float sQ[EE], sAttn[EE], sO[EE];
    __shared__ float sK[MM*129], sV[MM*129];

    if (e < MM) sIdx[e] = (e < ln) ? w2n[v*MM + e] : 0;
    __syncthreads();

    float qa = 0.f;
    for (int m = 0; m < ln; m++){
        int r = sIdx[m];
        qa += g_Q[r*EE + e];
        sK[m*129 + e] = g_K[r*EE + e];
        sV[m*129 + e] = g_V[r*EE + e];
    }
    sQ[e] = qa / (float)ln;
    __syncthreads();

    float s = -1e9f;
    if (lane < ln){
        s = 0.f;
        int base = h*32;
        #pragma unroll 8
        for (int d = 0; d < 32; d++)
            s += sQ[base + d] * sK[lane*129 + base + d];
        s *= 0.17677669529663687f;
    }
    float mx = s;
    #pragma unroll
    for (int o = 16; o > 0; o >>= 1) mx = fmaxf(mx, __shfl_xor_sync(0xffffffffu, mx, o));
    float ex = (lane < ln) ? __expf(s - mx) : 0.f;
    float sm = ex;
    #pragma unroll
    for (int o = 16; o > 0; o >>= 1) sm += __shfl_xor_sync(0xffffffffu, sm, o);
    sAttn[e] = ex / sm;
    __syncthreads();

    float oa = 0.f;
    for (int m = 0; m < ln; m++)
        oa += sAttn[h*32 + m] * sV[m*129 + e];
    sO[e] = oa;
    __syncthreads();

    float r = opb[e];
    const float4* w4 = (const float4*)(opw + (size_t)e*EE);
    const float4* o4 = (const float4*)sO;
    #pragma unroll 8
    for (int j = 0; j < EE/4; j++){
        float4 w = w4[j]; float4 o = o4[j];
        r += w.x*o.x + w.y*o.y + w.z*o.z + w.w*o.w;
    }
    g_wemb[v*EE + e] = r;
}

// ============================================================================
// Kernel 4: implicit-GEMM conv(3,4,5) + relu + maxpool + fc, fused.
// 256 threads / block, 2 blocks/SM. Thread tile 8t x 4c (16 f32x2 accs).
// Weight tiles [32e][128c] double-buffered via cp.async.
// Doc tile [70][132] padded; A loads broadcast, B loads conflict-free.
// ============================================================================
// smem float offsets
#define DOC_F   0                 // 70*132 = 9240
#define B0_F    9240              // 4096
#define B1_F    (9240+4096)       // 4096
#define PART_F  (9240+8192)       // 8*128 = 1024
#define POOL_F  (PART_F+1024)     // 384
#define SMEMF   (POOL_F+384)      // 18840 floats = 75360 bytes

__device__ __forceinline__ const float* chunk_src(int ci){
    // 48 chunks of 4096 floats: k=3 -> [0,12), k=4 -> [12,28), k=5 -> [28,48)
    if (ci < 12)  return g_wT + ci*4096;
    if (ci < 28)  return g_wT + 3*16384 + (ci-12)*4096;
    return g_wT + 7*16384 + (ci-28)*4096;
}

__global__ __launch_bounds__(256, 2)
void conv_kernel(const int*   __restrict__ nws,
                 const float* __restrict__ b3,
                 const float* __restrict__ b4,
                 const float* __restrict__ b5,
                 const float* __restrict__ fcw,
                 const float* __restrict__ fcb,
                 float*       __restrict__ out){
    extern __shared__ float sh[];
    int n = blockIdx.x, tid = threadIdx.x;
    int tt  = tid >> 5;          // 0..7
    int cc  = tid & 31;          // 0..31
    int tt8 = tt*8;
    uint32_t sbase = (uint32_t)__cvta_generic_to_shared(sh);

    // ---- stage doc tile [64][132] (gather), zero-pad rows 64..69 ----
    {
        const float4* src = (const float4*)g_wemb;
        float4* dst = (float4*)sh;
        #pragma unroll
        for (int q = 0; q < 8; q++){
            int idx = tid + q*256;           // 0..2047 over 64 rows x 32 f4
            int t = idx >> 5, e4 = idx & 31;
            int w = nws[n*LL + t];
            dst[t*33 + e4] = src[(size_t)w*32 + e4];
        }
        for (int i = tid; i < 6*132; i += 256) sh[64*132 + i] = 0.f;
    }

    // ---- prefetch chunk 0 ----
    {
        const float* s = chunk_src(0);
        uint32_t d = sbase + B0_F*4 + tid*16;
        #pragma unroll
        for (int q = 0; q < 4; q++) cpasync16(d + q*4096, s + tid*4 + q*1024);
        asm volatile("cp.async.commit_group;");
    }

    const float* biases[3] = {b3, b4, b5};
    ull acc[8][2];
    int ci = 0;

    for (int k = 0; k < 3; k++){
        const int K = 3 + k;
        #pragma unroll
        for (int i = 0; i < 8; i++){ acc[i][0] = 0ull; acc[i][1] = 0ull; }

        for (int jc = 0; jc < K*4; jc++, ci++){
            if (ci + 1 < 48){
                const float* s = chunk_src(ci+1);
                uint32_t d = sbase + (((ci+1)&1) ? B1_F : B0_F)*4 + tid*16;
                #pragma unroll
                for (int q = 0; q < 4; q++) cpasync16(d + q*4096, s + tid*4 + q*1024);
                asm volatile("cp.async.commit_group;");
                asm volatile("cp.async.wait_group 1;");
            } else {
                asm volatile("cp.async.wait_group 0;");
            }
            __syncthreads();

            int j = jc >> 2, ec = jc & 3;
            const float4* B4 = (const float4*)(sh + ((ci&1) ? B1_F : B0_F));
            const float4* D4 = ((const float4*)sh) + (tt8 + j)*33 + ec*8;

            #pragma unroll
            for (int es = 0; es < 8; es++){
                float4 a[8];
                #pragma unroll
                for (int i = 0; i < 8; i++) a[i] = D4[i*33 + es];
                #pragma unroll
                for (int x = 0; x < 4; x++){
                    float4 b = B4[(es*4 + x)*32 + cc];
                    ull b01 = pk2(b.x, b.y), b23 = pk2(b.z, b.w);
                    #pragma unroll
                    for (int i = 0; i < 8; i++){
                        float av = (x==0) ? a[i].x : (x==1) ? a[i].y
                                 : (x==2) ? a[i].z : a[i].w;
                        ull as = pk2(av, av);
                        ffma2(acc[i][0], as, b01);
                        ffma2(acc[i][1], as, b23);
                    }
                }
            }
            __syncthreads();
        }

        // ---- pool this k: masked max over thread's 8 t, then cross-tt ----
        float m0 = -3.4e38f, m1 = -3.4e38f, m2 = -3.4e38f, m3 = -3.4e38f;
        #pragma unroll
        for (int i = 0; i < 8; i++){
            if (tt8 + i <= LL - K){
                float x0,x1,x2,x3;
                upk2(acc[i][0], x0, x1);
                upk2(acc[i][1], x2, x3);
                m0 = fmaxf(m0, x0); m1 = fmaxf(m1, x1);
                m2 = fmaxf(m2, x2); m3 = fmaxf(m3, x3);
            }
        }
        sh[PART_F + tt*128 + cc*4 + 0] = m0;
        sh[PART_F + tt*128 + cc*4 + 1] = m1;
        sh[PART_F + tt*128 + cc*4 + 2] = m2;
        sh[PART_F + tt*128 + cc*4 + 3] = m3;
        __syncthreads();
        if (tid < 128){
            float m = sh[PART_F + tid];
            #pragma unroll
            for (int p = 1; p < 8; p++) m = fmaxf(m, sh[PART_F + p*128 + tid]);
            // max_t relu(y+b) == relu(b + max_t y)
            sh[POOL_F + k*128 + tid] = fmaxf(m + biases[k][tid], 0.f);
        }
        // next k's first chunk iteration begins with a __syncthreads(), which
        // protects PART_F reuse; POOL_F protected by the sync below before fc.
    }
    __syncthreads();

    // ---- fc: out[n][e] = fc_b[e] + pooled . fc_w[e] ----
    if (tid < 128){
        float acc2 = fcb[tid];
        const float4* w4 = (const float4*)(fcw + (size_t)tid*384);
        const float4* p4 = (const float4*)&sh[POOL_F];
        #pragma unroll 8
        for (int r = 0; r < 96; r++){
            float4 w = w4[r]; float4 p = p4[r];
            acc2 += w.x*p.x + w.y*p.y + w.z*p.z + w.w*p.w;
        }
        out[n*EE + tid] = acc2;
    }
}

// ============================================================================
extern "C" void kernel_launch(void* const* d_in, const int* in_sizes, int n_in,
                              void* d_out, int out_size){
    const int*   w2n   = (const int*)  d_in[0];
    const int*   w2nl  = (const int*)  d_in[1];
    const int*   nws   = (const int*)  d_in[2];
    const float* table = (const float*)d_in[3];
    const float* ipw   = (const float*)d_in[4];
    const float* ipb   = (const float*)d_in[5];
    const float* opw   = (const float*)d_in[6];
    const float* opb   = (const float*)d_in[7];
    const float* w3    = (const float*)d_in[8];
    const float* b3    = (const float*)d_in[9];
    const float* w4    = (const float*)d_in[10];
    const float* b4    = (const float*)d_in[11];
    const float* w5    = (const float*)d_in[12];
    const float* b5    = (const float*)d_in[13];
    const float* fcw   = (const float*)d_in[14];
    const float* fcb   = (const float*)d_in[15];
    float* out = (float*)d_out;

    cudaFuncSetAttribute(conv_kernel,
                         cudaFuncAttributeMaxDynamicSharedMemorySize,
                         SMEMF*4);

    proj_kernel  <<<NN, 128>>>(table, ipw, ipb);
    wtrans_kernel<<<768, 256>>>(w3, w4, w5);
    attn_kernel  <<<VSZ, 128>>>(w2n, w2nl, opw, opb);
    conv_kernel  <<<NN, 256, SMEMF*4>>>(nws, b3, b4, b5, fcw, fcb, out);
}

// round 8
// speedup vs baseline: 12.6846x; 1.9364x over previous
#include <cuda_runtime.h>
#include <cuda_bf16.h>
#include <cstdint>

#define VSZ 20000
#define MM  32
#define EE  128
#define NN  8192
#define LL  64

typedef unsigned long long ull;

// ---------------- scratch (device globals; no allocation allowed) -----------
__device__ float g_Q[NN*EE];
__device__ float g_K[NN*EE];
__device__ float g_V[NN*EE];
__device__ float g_wemb[VSZ*EE];
// conv weights: 12 slices x [hi/lo 32KB] x [n=128][k=128] bf16, XOR-swizzled
__device__ uint4 g_WB[786432/16];

// ---------------- helpers ----------------------------------------------------
__device__ __forceinline__ uint32_t s2u(const void* p){
    return (uint32_t)__cvta_generic_to_shared(p);
}
__device__ __forceinline__ void cp16(uint32_t d, const void* s){
    asm volatile("cp.async.cg.shared.global [%0], [%1], 16;" :: "r"(d), "l"(s));
}
__device__ __forceinline__ void ldsm4(uint32_t* r, uint32_t addr){
    asm volatile("ldmatrix.sync.aligned.m8n8.x4.shared.b16 {%0,%1,%2,%3}, [%4];"
        : "=r"(r[0]), "=r"(r[1]), "=r"(r[2]), "=r"(r[3]) : "r"(addr));
}
__device__ __forceinline__ void mma16816(float* c, const uint32_t* a, const uint32_t* b){
    asm volatile("mma.sync.aligned.m16n8k16.row.col.f32.bf16.bf16.f32 "
        "{%0,%1,%2,%3}, {%4,%5,%6,%7}, {%8,%9}, {%0,%1,%2,%3};"
        : "+f"(c[0]), "+f"(c[1]), "+f"(c[2]), "+f"(c[3])
        : "r"(a[0]), "r"(a[1]), "r"(a[2]), "r"(a[3]), "r"(b[0]), "r"(b[1]));
}
__device__ __forceinline__ void split8(float4 a, float4 b, uint4 &H, uint4 &L){
    float v[8] = {a.x,a.y,a.z,a.w,b.x,b.y,b.z,b.w};
    uint32_t h[8], l[8];
    #pragma unroll
    for (int i = 0; i < 8; i++){
        __nv_bfloat16 hb = __float2bfloat16_rn(v[i]);
        float rest = v[i] - __bfloat162float(hb);
        __nv_bfloat16 lb = __float2bfloat16_rn(rest);
        h[i] = (uint32_t)__bfloat16_as_ushort(hb);
        l[i] = (uint32_t)__bfloat16_as_ushort(lb);
    }
    H.x = h[0]|(h[1]<<16); H.y = h[2]|(h[3]<<16);
    H.z = h[4]|(h[5]<<16); H.w = h[6]|(h[7]<<16);
    L.x = l[0]|(l[1]<<16); L.y = l[2]|(l[3]<<16);
    L.z = l[4]|(l[5]<<16); L.w = l[6]|(l[7]<<16);
}

// ============================================================================
// Kernel 1: project news table once: Qn/Kn/Vn = table @ W.T + b
// ============================================================================
__global__ void proj_kernel(const float* __restrict__ table,
                            const float* __restrict__ ipw,
                            const float* __restrict__ ipb){
    int n = blockIdx.x, e = threadIdx.x;
    __shared__ float4 sX[EE/4];
    ((float*)sX)[e] = table[n*EE + e];
    __syncthreads();
    const float4* rq = (const float4*)(ipw + (size_t)e*EE);
    const float4* rk = (const float4*)(ipw + (size_t)(EE + e)*EE);
    const float4* rv = (const float4*)(ipw + (size_t)(2*EE + e)*EE);
    float aq = 0.f, ak = 0.f, av = 0.f;
    #pragma unroll 8
    for (int j = 0; j < EE/4; j++){
        float4 x = sX[j];
        float4 q = rq[j], k = rk[j], v = rv[j];
        aq += q.x*x.x + q.y*x.y + q.z*x.z + q.w*x.w;
        ak += k.x*x.x + k.y*x.y + k.z*x.z + k.w*x.w;
        av += v.x*x.x + v.y*x.y + v.z*x.z + v.w*x.w;
    }
    g_Q[n*EE+e] = aq + ipb[e];
    g_K[n*EE+e] = ak + ipb[EE + e];
    g_V[n*EE+e] = av + ipb[2*EE + e];
}

// ============================================================================
// Kernel 2: bake conv weights -> bf16 hi/lo, [slice][plane][n][k] XOR-swizzled
// slice s: k=3 -> j=s (s<3); k=4 -> j=s-3 (s<7); k=5 -> j=s-7.
// byte = s*65536 + plane*32768 + n*256 + phys_chunk*16 + (e&7)*2,
// phys_chunk = (ck&8) | ((ck&7) ^ (n&7)),  ck = e>>3.
// ============================================================================
__global__ void wprep_kernel(const float* __restrict__ w3,
                             const float* __restrict__ w4,
                             const float* __restrict__ w5){
    int idx = blockIdx.x*256 + threadIdx.x;
    if (idx >= 196608) return;
    int s = idx >> 14, rem = idx & 16383;
    int n = rem >> 7, e = rem & 127;      // n = out channel, e = input dim
    int k, j; const float* w;
    if (s < 3){ k = 3; j = s;     w = w3; }
    else if (s < 7){ k = 4; j = s - 3; w = w4; }
    else { k = 5; j = s - 7; w = w5; }
    float x = w[(n*EE + e)*k + j];
    __nv_bfloat16 hb = __float2bfloat16_rn(x);
    __nv_bfloat16 lb = __float2bfloat16_rn(x - __bfloat162float(hb));
    int ck = e >> 3;
    int phys = (ck & 8) | ((ck & 7) ^ (n & 7));
    size_t base = (size_t)s*65536 + (size_t)n*256 + (size_t)phys*16 + (size_t)(e&7)*2;
    char* g = (char*)g_WB;
    *(unsigned short*)(g + base)         = __bfloat16_as_ushort(hb);
    *(unsigned short*)(g + base + 32768) = __bfloat16_as_ushort(lb);
}

// ============================================================================
// Kernel 3: per-word 1-query MHA using precomputed projected tables.
// ============================================================================
__global__ void attn_kernel(const int* __restrict__ w2n,
                            const int* __restrict__ w2nlen,
                            const float* __restrict__ opw,
                            const float* __restrict__ opb){
    int v = blockIdx.x, e = threadIdx.x;
    int h = e >> 5, lane = e & 31;
    int ln = w2nlen[v];
    if (ln == 0){ g_wemb[v*EE + e] = 0.f; return; }

    __shared__ int   sIdx[MM];
    __shared__ float sQ[EE], sAttn[EE], sO[EE];
    __shared__ float sK[MM*129], sV[MM*129];

    if (e < MM) sIdx[e] = (e < ln) ? w2n[v*MM + e] : 0;
    __syncthreads();

    float qa = 0.f;
    for (int m = 0; m < ln; m++){
        int r = sIdx[m];
        qa += g_Q[r*EE + e];
        sK[m*129 + e] = g_K[r*EE + e];
        sV[m*129 + e] = g_V[r*EE + e];
    }
    sQ[e] = qa / (float)ln;
    __syncthreads();

    float s = -1e9f;
    if (lane < ln){
        s = 0.f;
        int base = h*32;
        #pragma unroll 8
        for (int d = 0; d < 32; d++)
            s += sQ[base + d] * sK[lane*129 + base + d];
        s *= 0.17677669529663687f;
    }
    float mx = s;
    #pragma unroll
    for (int o = 16; o > 0; o >>= 1) mx = fmaxf(mx, __shfl_xor_sync(0xffffffffu, mx, o));
    float ex = (lane < ln) ? __expf(s - mx) : 0.f;
    float sm = ex;
    #pragma unroll
    for (int o = 16; o > 0; o >>= 1) sm += __shfl_xor_sync(0xffffffffu, sm, o);
    sAttn[e] = ex / sm;
    __syncthreads();

    float oa = 0.f;
    for (int m = 0; m < ln; m++)
        oa += sAttn[h*32 + m] * sV[m*129 + e];
    sO[e] = oa;
    __syncthreads();

    float r = opb[e];
    const float4* w4 = (const float4*)(opw + (size_t)e*EE);
    const float4* o4 = (const float4*)sO;
    #pragma unroll 8
    for (int j = 0; j < EE/4; j++){
        float4 w = w4[j]; float4 o = o4[j];
        r += w.x*o.x + w.y*o.y + w.z*o.z + w.w*o.w;
    }
    g_wemb[v*EE + e] = r;
}

// ============================================================================
// Kernel 4: mma.sync bf16 hi/lo implicit-GEMM conv + relu + maxpool + fc.
// CTA = 2 docs: M=128 (rows = doc*68-row layout), N=128 channels.
// Warp tile 32m x 64n (mblock = w&3, nblock = w>>2). 8 warps.
// A built once in smem (hi/lo planes, 272B stride); tap j = +272*j offset.
// Weights streamed per j-slice (64KB hi+lo) via double-buffered cp.async.
// 3 passes: AhBh + AhBl + AlBh into fp32 acc regs.
// ============================================================================
#define SM_AH   0
#define SM_AL   36992               // 136 rows * 272B
#define SM_W    73984               // 2 x 65536 ring
#define SM_PART 205056              // 8 warps x 64 floats
#define SM_POOL 207104              // 2 x 384 floats
#define SM_TOT  210176

__global__ __launch_bounds__(256, 1)
void conv_kernel(const int*   __restrict__ nws,
                 const float* __restrict__ b3,
                 const float* __restrict__ b4,
                 const float* __restrict__ b5,
                 const float* __restrict__ fcw,
                 const float* __restrict__ fcb,
                 float*       __restrict__ out){
    extern __shared__ char shb[];
    float* shf = (float*)shb;
    const int bid = blockIdx.x, tid = threadIdx.x;
    const int w = tid >> 5, lane = tid & 31;
    const int mb = w & 3, nb = w >> 2, d = mb >> 1;
    const uint32_t sb = s2u(shb);

    // ---- gather doc rows, split to bf16 hi/lo planes ----
    #pragma unroll
    for (int it = 0; it < 8; it++){
        int idx = tid + it*256;            // 128 rows x 16 octs
        int row = idx >> 4, oct = idx & 15;
        int wd = nws[bid*128 + row];
        const float4* s = (const float4*)(g_wemb + (size_t)wd*EE) + oct*2;
        uint4 H, L;
        split8(s[0], s[1], H, L);
        int srow = (row >> 6)*68 + (row & 63);
        *(uint4*)(shb + SM_AH + srow*272 + oct*16) = H;
        *(uint4*)(shb + SM_AL + srow*272 + oct*16) = L;
    }
    // zero-pad rows 64..67 of each doc (all 17 chunks incl row pad)
    for (int i = tid; i < 2*4*17; i += 256){
        int dd = i / 68, rem = i - dd*68;
        int r = rem / 17, c4 = rem % 17;
        int srow = dd*68 + 64 + r;
        *(uint4*)(shb + SM_AH + srow*272 + c4*16) = make_uint4(0,0,0,0);
        *(uint4*)(shb + SM_AL + srow*272 + c4*16) = make_uint4(0,0,0,0);
    }

    // ---- per-thread ldmatrix address precompute ----
    const int khalf = (lane >> 3) & 1;
    int n7[4]; uint32_t rbB[4];
    #pragma unroll
    for (int p = 0; p < 4; p++){
        int n = nb*64 + p*16 + (((lane >> 3) >= 2) ? 8 : 0) + (lane & 7);
        n7[p]  = n & 7;
        rbB[p] = (uint32_t)n * 256;
    }
    const int tl = (mb & 1)*32;
    const uint32_t aBase = sb + SM_AH
        + (uint32_t)(d*68 + tl + (lane & 15))*272 + (uint32_t)(lane >> 4)*16;

    // ---- prefetch slice 0 ----
    {
        const char* src = (const char*)g_WB + tid*16;
        uint32_t dst = sb + SM_W + tid*16;
        #pragma unroll
        for (int q = 0; q < 16; q++) cp16(dst + q*4096, src + q*4096);
        asm volatile("cp.async.commit_group;");
    }

    float acc[2][8][4];
    float* part = shf + SM_PART/4;
    float* pool = shf + SM_POOL/4;

    int ci = 0;
    for (int kk = 0; kk < 3; kk++){
        const int Kk = kk + 3;
        #pragma unroll
        for (int mt = 0; mt < 2; mt++)
            #pragma unroll
            for (int nt = 0; nt < 8; nt++)
                #pragma unroll
                for (int i = 0; i < 4; i++) acc[mt][nt][i] = 0.f;

        for (int j = 0; j < Kk; j++, ci++){
            if (ci + 1 < 12){
                const char* src = (const char*)g_WB + (size_t)(ci+1)*65536 + tid*16;
                uint32_t dst = sb + SM_W + (uint32_t)((ci+1)&1)*65536 + tid*16;
                #pragma unroll
                for (int q = 0; q < 16; q++) cp16(dst + q*4096, src + q*4096);
                asm volatile("cp.async.commit_group;");
                asm volatile("cp.async.wait_group 1;");
            } else {
                asm volatile("cp.async.wait_group 0;");
            }
            __syncthreads();

            const uint32_t wbuf = sb + SM_W + (uint32_t)(ci & 1)*65536;
            const uint32_t aj = aBase + (uint32_t)j*272;

            #pragma unroll
            for (int ks = 0; ks < 8; ks++){
                uint32_t aH0[4], aH1[4], aL0[4], aL1[4];
                ldsm4(aH0, aj + ks*32);
                ldsm4(aH1, aj + 16*272 + ks*32);
                ldsm4(aL0, aj + (SM_AL - SM_AH) + ks*32);
                ldsm4(aL1, aj + (SM_AL - SM_AH) + 16*272 + ks*32);
                uint32_t bH[4][4], bL[4][4];
                #pragma unroll
                for (int p = 0; p < 4; p++){
                    int ck = ks*2 + khalf;
                    int phys = (ck & 8) | ((ck & 7) ^ n7[p]);
                    uint32_t ad = wbuf + rbB[p] + (uint32_t)phys*16;
                    ldsm4(bH[p], ad);
                    ldsm4(bL[p], ad + 32768);
                }
                #pragma unroll
                for (int mt = 0; mt < 2; mt++){
                    const uint32_t* ah = mt ? aH1 : aH0;
                    const uint32_t* al = mt ? aL1 : aL0;
                    #pragma unroll
                    for (int p = 0; p < 4; p++){
                        #pragma unroll
                        for (int h = 0; h < 2; h++){
                            float* c = acc[mt][p*2 + h];
                            mma16816(c, ah, &bH[p][h*2]);
                            mma16816(c, ah, &bL[p][h*2]);
                            mma16816(c, al, &bH[p][h*2]);
                        }
                    }
                }
            }
            __syncthreads();
        }

        // ---- epilogue for this kernel size: masked max over t ----
        const float* bias = (kk == 0) ? b3 : (kk == 1) ? b4 : b5;
        #pragma unroll
        for (int nt = 0; nt < 8; nt++){
            float m0 = -3.4e38f, m1 = -3.4e38f;
            #pragma unroll
            for (int mt = 0; mt < 2; mt++){
                int tb = tl + mt*16 + (lane >> 2);
                if (tb <= LL - Kk){
                    m0 = fmaxf(m0, acc[mt][nt][0]);
                    m1 = fmaxf(m1, acc[mt][nt][1]);
                }
                if (tb + 8 <= LL - Kk){
                    m0 = fmaxf(m0, acc[mt][nt][2]);
                    m1 = fmaxf(m1, acc[mt][nt][3]);
                }
            }
            #pragma unroll
            for (int s = 4; s < 32; s <<= 1){
                m0 = fmaxf(m0, __shfl_xor_sync(0xffffffffu, m0, s));
                m1 = fmaxf(m1, __shfl_xor_sync(0xffffffffu, m1, s));
            }
            if (lane < 4){
                part[w*64 + nt*8 + (lane & 3)*2 + 0] = m0;
                part[w*64 + nt*8 + (lane & 3)*2 + 1] = m1;
            }
        }
        __syncthreads();
        {
            int dd = tid >> 7, col = tid & 127;
            int w0 = (col >> 6)*4 + dd*2;
            float v = fmaxf(part[w0*64 + (col & 63)], part[(w0+1)*64 + (col & 63)]);
            // max_t relu(y+b) == relu(b + max_t y)
            pool[dd*384 + kk*128 + col] = fmaxf(v + bias[col], 0.f);
        }
        __syncthreads();
    }

    // ---- fc: out[n][e] = fc_b[e] + pooled . fc_w[e] ----
    {
        int dd = tid >> 7, e = tid & 127;
        float a = fcb[e];
        const float4* w4 = (const float4*)(fcw + (size_t)e*384);
        const float4* p4 = (const float4*)(pool + dd*384);
        #pragma unroll 8
        for (int r = 0; r < 96; r++){
            float4 ww = w4[r]; float4 pp = p4[r];
            a += ww.x*pp.x + ww.y*pp.y + ww.z*pp.z + ww.w*pp.w;
        }
        out[(size_t)(2*bid + dd)*EE + e] = a;
    }
}

// ============================================================================
extern "C" void kernel_launch(void* const* d_in, const int* in_sizes, int n_in,
                              void* d_out, int out_size){
    const int*   w2n   = (const int*)  d_in[0];
    const int*   w2nl  = (const int*)  d_in[1];
    const int*   nws   = (const int*)  d_in[2];
    const float* table = (const float*)d_in[3];
    const float* ipw   = (const float*)d_in[4];
    const float* ipb   = (const float*)d_in[5];
    const float* opw   = (const float*)d_in[6];
    const float* opb   = (const float*)d_in[7];
    const float* w3    = (const float*)d_in[8];
    const float* b3    = (const float*)d_in[9];
    const float* w4    = (const float*)d_in[10];
    const float* b4    = (const float*)d_in[11];
    const float* w5    = (const float*)d_in[12];
    const float* b5    = (const float*)d_in[13];
    const float* fcw   = (const float*)d_in[14];
    const float* fcb   = (const float*)d_in[15];
    float* out = (float*)d_out;

    cudaFuncSetAttribute(conv_kernel,
                         cudaFuncAttributeMaxDynamicSharedMemorySize, SM_TOT);

    proj_kernel <<<NN, 128>>>(table, ipw, ipb);
    wprep_kernel<<<768, 256>>>(w3, w4, w5);
    attn_kernel <<<VSZ, 128>>>(w2n, w2nl, opw, opb);
    conv_kernel <<<NN/2, 256, SM_TOT>>>(nws, b3, b4, b5, fcw, fcb, out);
}

// round 9
// speedup vs baseline: 25.1217x; 1.9805x over previous
#include <cuda_runtime.h>
#include <cuda_fp16.h>
#include <cstdint>

#define VSZ 20000
#define MM  32
#define EE  128
#define NN  8192
#define LL  64

typedef unsigned long long ull;

// ---------------- scratch (device globals; no allocation allowed) -----------
__device__ float g_Q[NN*EE];
__device__ float g_K[NN*EE];
__device__ float g_V[NN*EE];
__device__ float g_wemb[VSZ*EE];
// conv weights: 12 slices x 32KB fp16 [n=128][k=128], XOR-swizzled
__device__ uint4 g_WB[393216/16];

// ---------------- helpers ----------------------------------------------------
__device__ __forceinline__ uint32_t s2u(const void* p){
    return (uint32_t)__cvta_generic_to_shared(p);
}
__device__ __forceinline__ void cp16(uint32_t d, const void* s){
    asm volatile("cp.async.cg.shared.global [%0], [%1], 16;" :: "r"(d), "l"(s));
}
__device__ __forceinline__ void ldsm4(uint32_t* r, uint32_t addr){
    asm volatile("ldmatrix.sync.aligned.m8n8.x4.shared.b16 {%0,%1,%2,%3}, [%4];"
        : "=r"(r[0]), "=r"(r[1]), "=r"(r[2]), "=r"(r[3]) : "r"(addr));
}
__device__ __forceinline__ void mma16816(float* c, const uint32_t* a, const uint32_t* b){
    asm volatile("mma.sync.aligned.m16n8k16.row.col.f32.f16.f16.f32 "
        "{%0,%1,%2,%3}, {%4,%5,%6,%7}, {%8,%9}, {%0,%1,%2,%3};"
        : "+f"(c[0]), "+f"(c[1]), "+f"(c[2]), "+f"(c[3])
        : "r"(a[0]), "r"(a[1]), "r"(a[2]), "r"(a[3]), "r"(b[0]), "r"(b[1]));
}
__device__ __forceinline__ uint32_t f2h2(float a, float b){
    __half2 h = __floats2half2_rn(a, b);
    return *(uint32_t*)&h;
}

// ============================================================================
// Kernel 1: project news table: Qn/Kn/Vn = table @ W.T + b
// 1024 blocks x 384 threads; 8 docs per block; each thread owns one output
// column o of the 384 (q|k|v) and keeps the weight element in a register
// across all 8 docs (X broadcast from smem).
// ============================================================================
__global__ void proj_kernel(const float* __restrict__ table,
                            const float* __restrict__ ipw,
                            const float* __restrict__ ipb){
    __shared__ float sX[8*EE];
    int tid = threadIdx.x;
    int n0 = blockIdx.x*8;
    for (int i = tid; i < 8*EE; i += 384)
        sX[i] = table[(size_t)(n0 + (i >> 7))*EE + (i & 127)];
    __syncthreads();

    int o = tid;                               // 0..383
    const float4* wr = (const float4*)(ipw + (size_t)o*EE);
    float acc[8];
    #pragma unroll
    for (int n = 0; n < 8; n++) acc[n] = 0.f;
    #pragma unroll 4
    for (int j = 0; j < 32; j++){
        float4 wv = wr[j];
        #pragma unroll
        for (int n = 0; n < 8; n++){
            float4 x = ((const float4*)(sX + n*EE))[j];
            acc[n] += wv.x*x.x + wv.y*x.y + wv.z*x.z + wv.w*x.w;
        }
    }
    float b = ipb[o];
    float* dst = (o < 128) ? g_Q : (o < 256) ? g_K : g_V;
    int col = o & 127;
    #pragma unroll
    for (int n = 0; n < 8; n++)
        dst[(size_t)(n0 + n)*EE + col] = acc[n] + b;
}

// ============================================================================
// Kernel 2: bake conv weights -> fp16, [slice][n][k] XOR-swizzled.
// slice s: k=3 -> j=s (s<3); k=4 -> j=s-3 (s<7); k=5 -> j=s-7.
// byte = s*32768 + n*256 + phys*16 + (e&7)*2,
// phys = (ck&8) | ((ck&7) ^ (n&7)),  ck = e>>3.
// ============================================================================
__global__ void wprep_kernel(const float* __restrict__ w3,
                             const float* __restrict__ w4,
                             const float* __restrict__ w5){
    int idx = blockIdx.x*256 + threadIdx.x;
    if (idx >= 196608) return;
    int s = idx >> 14, rem = idx & 16383;
    int n = rem >> 7, e = rem & 127;
    int k, j; const float* w;
    if (s < 3){ k = 3; j = s;     w = w3; }
    else if (s < 7){ k = 4; j = s - 3; w = w4; }
    else { k = 5; j = s - 7; w = w5; }
    __half h = __float2half_rn(w[(n*EE + e)*k + j]);
    int ck = e >> 3;
    int phys = (ck & 8) | ((ck & 7) ^ (n & 7));
    size_t base = (size_t)s*32768 + (size_t)n*256 + (size_t)phys*16 + (size_t)(e&7)*2;
    *(unsigned short*)((char*)g_WB + base) = __half_as_ushort(h);
}

// ============================================================================
// Kernel 3: per-word 1-query MHA using precomputed projected tables.
// V read directly from L2 during the AV stage (no staging), 4-way MLP.
// ============================================================================
__global__ void attn_kernel(const int* __restrict__ w2n,
                            const int* __restrict__ w2nlen,
                            const float* __restrict__ opw,
                            const float* __restrict__ opb){
    int v = blockIdx.x, e = threadIdx.x;
    int h = e >> 5, lane = e & 31;
    int ln = w2nlen[v];
    if (ln == 0){ g_wemb[v*EE + e] = 0.f; return; }

    __shared__ int   sIdx[MM];
    __shared__ float sQ[EE], sAttn[EE], sO[EE];
    __shared__ float sK[MM*129];

    if (e < MM) sIdx[e] = (e < ln) ? w2n[v*MM + e] : 0;
    __syncthreads();

    float qa = 0.f;
    {
        int m = 0;
        for (; m + 2 <= ln; m += 2){
            int r0 = sIdx[m], r1 = sIdx[m+1];
            float q0 = g_Q[r0*EE + e], q1 = g_Q[r1*EE + e];
            sK[m*129 + e]     = g_K[r0*EE + e];
            sK[(m+1)*129 + e] = g_K[r1*EE + e];
            qa += q0 + q1;
        }
        if (m < ln){
            int r = sIdx[m];
            qa += g_Q[r*EE + e];
            sK[m*129 + e] = g_K[r*EE + e];
        }
    }
    sQ[e] = qa / (float)ln;
    __syncthreads();

    float s = -1e9f;
    if (lane < ln){
        s = 0.f;
        int base = h*32;
        #pragma unroll 8
        for (int d = 0; d < 32; d++)
            s += sQ[base + d] * sK[lane*129 + base + d];
        s *= 0.17677669529663687f;
    }
    float mx = s;
    #pragma unroll
    for (int o = 16; o > 0; o >>= 1) mx = fmaxf(mx, __shfl_xor_sync(0xffffffffu, mx, o));
    float ex = (lane < ln) ? __expf(s - mx) : 0.f;
    float sm = ex;
    #pragma unroll
    for (int o = 16; o > 0; o >>= 1) sm += __shfl_xor_sync(0xffffffffu, sm, o);
    sAttn[e] = ex / sm;
    __syncthreads();

    float oa = 0.f;
    {
        int m = 0;
        for (; m + 4 <= ln; m += 4){
            float a0 = sAttn[h*32 + m]     * g_V[sIdx[m]*EE + e];
            float a1 = sAttn[h*32 + m + 1] * g_V[sIdx[m+1]*EE + e];
            float a2 = sAttn[h*32 + m + 2] * g_V[sIdx[m+2]*EE + e];
            float a3 = sAttn[h*32 + m + 3] * g_V[sIdx[m+3]*EE + e];
            oa += (a0 + a1) + (a2 + a3);
        }
        for (; m < ln; m++)
            oa += sAttn[h*32 + m] * g_V[sIdx[m]*EE + e];
    }
    sO[e] = oa;
    __syncthreads();

    float r = opb[e];
    const float4* w4 = (const float4*)(opw + (size_t)e*EE);
    const float4* o4 = (const float4*)sO;
    #pragma unroll 8
    for (int j = 0; j < EE/4; j++){
        float4 w = w4[j]; float4 o = o4[j];
        r += w.x*o.x + w.y*o.y + w.z*o.z + w.w*o.w;
    }
    g_wemb[v*EE + e] = r;
}

// ============================================================================
// Kernel 4: single-pass fp16 mma.sync implicit-GEMM conv + relu + maxpool + fc.
// CTA = 2 docs: M=128 (doc*68-row layout), N=128 channels. 8 warps,
// warp tile 32m x 64n. 2 CTAs/SM. A built once in smem fp16 (272B stride);
// tap j = +272*j offset. Weights streamed per j-slice (32KB) double-buffered.
// ============================================================================
#define SM_A    0                   // 136 rows * 272B = 36992
#define SM_W    36992               // 2 x 32768 ring
#define SM_PART 102528              // 8 warps x 64 floats
#define SM_POOL 104576              // 2 x 384 floats
#define SM_TOT  107648

__global__ __launch_bounds__(256, 2)
void conv_kernel(const int*   __restrict__ nws,
                 const float* __restrict__ b3,
                 const float* __restrict__ b4,
                 const float* __restrict__ b5,
                 const float* __restrict__ fcw,
                 const float* __restrict__ fcb,
                 float*       __restrict__ out){
    extern __shared__ char shb[];
    float* shf = (float*)shb;
    const int bid = blockIdx.x, tid = threadIdx.x;
    const int w = tid >> 5, lane = tid & 31;
    const int mb = w & 3, nb = w >> 2, d = mb >> 1;
    const uint32_t sb = s2u(shb);

    // ---- gather doc rows, convert to fp16 ----
    #pragma unroll
    for (int it = 0; it < 8; it++){
        int idx = tid + it*256;            // 128 rows x 16 octs
        int row = idx >> 4, oct = idx & 15;
        int wd = nws[bid*128 + row];
        const float4* s = (const float4*)(g_wemb + (size_t)wd*EE) + oct*2;
        float4 s0 = s[0], s1 = s[1];
        uint4 H;
        H.x = f2h2(s0.x, s0.y); H.y = f2h2(s0.z, s0.w);
        H.z = f2h2(s1.x, s1.y); H.w = f2h2(s1.z, s1.w);
        int srow = (row >> 6)*68 + (row & 63);
        *(uint4*)(shb + SM_A + srow*272 + oct*16) = H;
    }
    // zero-pad rows 64..67 of each doc
    for (int i = tid; i < 2*4*17; i += 256){
        int dd = i / 68, rem = i - dd*68;
        int r = rem / 17, c4 = rem % 17;
        int srow = dd*68 + 64 + r;
        *(uint4*)(shb + SM_A + srow*272 + c4*16) = make_uint4(0,0,0,0);
    }

    // ---- per-thread ldmatrix address precompute ----
    const int khalf = (lane >> 3) & 1;
    int n7[4]; uint32_t rbB[4];
    #pragma unroll
    for (int p = 0; p < 4; p++){
        int n = nb*64 + p*16 + (((lane >> 3) >= 2) ? 8 : 0) + (lane & 7);
        n7[p]  = n & 7;
        rbB[p] = (uint32_t)n * 256;
    }
    const int tl = (mb & 1)*32;
    const uint32_t aBase = sb + SM_A
        + (uint32_t)(d*68 + tl + (lane & 15))*272 + (uint32_t)(lane >> 4)*16;

    // ---- prefetch slice 0 (32KB) ----
    {
        const char* src = (const char*)g_WB + tid*16;
        uint32_t dst = sb + SM_W + tid*16;
        #pragma unroll
        for (int q = 0; q < 8; q++) cp16(dst + q*4096, src + q*4096);
        asm volatile("cp.async.commit_group;");
    }

    float acc[2][8][4];
    float* part = shf + SM_PART/4;
    float* pool = shf + SM_POOL/4;

    int ci = 0;
    for (int kk = 0; kk < 3; kk++){
        const int Kk = kk + 3;
        #pragma unroll
        for (int mt = 0; mt < 2; mt++)
            #pragma unroll
            for (int nt = 0; nt < 8; nt++)
                #pragma unroll
                for (int i = 0; i < 4; i++) acc[mt][nt][i] = 0.f;

        for (int j = 0; j < Kk; j++, ci++){
            if (ci + 1 < 12){
                const char* src = (const char*)g_WB + (size_t)(ci+1)*32768 + tid*16;
                uint32_t dst = sb + SM_W + (uint32_t)((ci+1)&1)*32768 + tid*16;
                #pragma unroll
                for (int q = 0; q < 8; q++) cp16(dst + q*4096, src + q*4096);
                asm volatile("cp.async.commit_group;");
                asm volatile("cp.async.wait_group 1;");
            } else {
                asm volatile("cp.async.wait_group 0;");
            }
            __syncthreads();

            const uint32_t wbuf = sb + SM_W + (uint32_t)(ci & 1)*32768;
            const uint32_t aj = aBase + (uint32_t)j*272;

            #pragma unroll
            for (int ks = 0; ks < 8; ks++){
                uint32_t a0[4], a1[4];
                ldsm4(a0, aj + ks*32);
                ldsm4(a1, aj + 16*272 + ks*32);
                uint32_t B[4][4];
                #pragma unroll
                for (int p = 0; p < 4; p++){
                    int ck = ks*2 + khalf;
                    int phys = (ck & 8) | ((ck & 7) ^ n7[p]);
                    ldsm4(B[p], wbuf + rbB[p] + (uint32_t)phys*16);
                }
                #pragma unroll
                for (int mt = 0; mt < 2; mt++){
                    const uint32_t* a = mt ? a1 : a0;
                    #pragma unroll
                    for (int p = 0; p < 4; p++){
                        #pragma unroll
                        for (int h = 0; h < 2; h++)
                            mma16816(acc[mt][p*2 + h], a, &B[p][h*2]);
                    }
                }
            }
            __syncthreads();
        }

        // ---- epilogue for this kernel size: masked max over t ----
        const float* bias = (kk == 0) ? b3 : (kk == 1) ? b4 : b5;
        #pragma unroll
        for (int nt = 0; nt < 8; nt++){
            float m0 = -3.4e38f, m1 = -3.4e38f;
            #pragma unroll
            for (int mt = 0; mt < 2; mt++){
                int tb = tl + mt*16 + (lane >> 2);
                if (tb <= LL - Kk){
                    m0 = fmaxf(m0, acc[mt][nt][0]);
                    m1 = fmaxf(m1, acc[mt][nt][1]);
                }
                if (tb + 8 <= LL - Kk){
                    m0 = fmaxf(m0, acc[mt][nt][2]);
                    m1 = fmaxf(m1, acc[mt][nt][3]);
                }
            }
            #pragma unroll
            for (int s = 4; s < 32; s <<= 1){
                m0 = fmaxf(m0, __shfl_xor_sync(0xffffffffu, m0, s));
                m1 = fmaxf(m1, __shfl_xor_sync(0xffffffffu, m1, s));
            }
            if (lane < 4){
                part[w*64 + nt*8 + (lane & 3)*2 + 0] = m0;
                part[w*64 + nt*8 + (lane & 3)*2 + 1] = m1;
            }
        }
        __syncthreads();
        {
            int dd = tid >> 7, col = tid & 127;
            int w0 = (col >> 6)*4 + dd*2;
            float v = fmaxf(part[w0*64 + (col & 63)], part[(w0+1)*64 + (col & 63)]);
            // max_t relu(y+b) == relu(b + max_t y)
            pool[dd*384 + kk*128 + col] = fmaxf(v + bias[col], 0.f);
        }
        __syncthreads();
    }

    // ---- fc: out[n][e] = fc_b[e] + pooled . fc_w[e] ----
    {
        int dd = tid >> 7, e = tid & 127;
        float a = fcb[e];
        const float4* w4 = (const float4*)(fcw + (size_t)e*384);
        const float4* p4 = (const float4*)(pool + dd*384);
        #pragma unroll 8
        for (int r = 0; r < 96; r++){
            float4 ww = w4[r]; float4 pp = p4[r];
            a += ww.x*pp.x + ww.y*pp.y + ww.z*pp.z + ww.w*pp.w;
        }
        out[(size_t)(2*bid + dd)*EE + e] = a;
    }
}

// ============================================================================
extern "C" void kernel_launch(void* const* d_in, const int* in_sizes, int n_in,
                              void* d_out, int out_size){
    const int*   w2n   = (const int*)  d_in[0];
    const int*   w2nl  = (const int*)  d_in[1];
    const int*   nws   = (const int*)  d_in[2];
    const float* table = (const float*)d_in[3];
    const float* ipw   = (const float*)d_in[4];
    const float* ipb   = (const float*)d_in[5];
    const float* opw   = (const float*)d_in[6];
    const float* opb   = (const float*)d_in[7];
    const float* w3    = (const float*)d_in[8];
    const float* b3    = (const float*)d_in[9];
    const float* w4    = (const float*)d_in[10];
    const float* b4    = (const float*)d_in[11];
    const float* w5    = (const float*)d_in[12];
    const float* b5    = (const float*)d_in[13];
    const float* fcw   = (const float*)d_in[14];
    const float* fcb   = (const float*)d_in[15];
    float* out = (float*)d_out;

    cudaFuncSetAttribute(conv_kernel,
                         cudaFuncAttributeMaxDynamicSharedMemorySize, SM_TOT);

    proj_kernel <<<NN/8, 384>>>(table, ipw, ipb);
    wprep_kernel<<<768, 256>>>(w3, w4, w5);
    attn_kernel <<<VSZ, 128>>>(w2n, w2nl, opw, opb);
    conv_kernel <<<NN/2, 256, SM_TOT>>>(nws, b3, b4, b5, fcw, fcb, out);
}